// round 10
// baseline (speedup 1.0000x reference)
#include <cuda_runtime.h>
#include <math.h>

#define Bb    16
#define Nn    1024
#define Uu    64
#define MAXD  256
#define ALPHAF 0.2f
#define ROWS  (Bb*Nn)
#define G1_BLOCKS (ROWS / 64)      /* 256 gemm1 blocks */
#define CSR_BLOCKS (Nn / 4)        /* 256 csr blocks, 4 warps each */

// ---------------- scratch (device globals; no allocation allowed) ----------
__device__ float g_h1[ROWS * 128];   // layer-1 features  (8 MB)
__device__ float g_h2[ROWS * 64];    // layer-2 features  (4 MB)
__device__ float g_rs[ROWS * 64];    // r * state         (4 MB)
__device__ float g_z [ROWS * 64];    // z gate            (4 MB)
__device__ float g_s1s[ROWS], g_s1d[ROWS];
__device__ float g_s2s[ROWS], g_s2d[ROWS];
__device__ int   g_cols[Nn * MAXD];
__device__ int   g_deg [Nn];

__device__ __forceinline__ float lrelu(float x) { return x > 0.f ? x : ALPHAF * x; }

// ---------------- fused GEMM1 + CSR build ----------------------------------
// blocks [0,256): h1 = [X|state] @ W1 + fused scores (8x8/thread, dbl-buffered)
// blocks [256,512): CSR build, 4 warps/block, one adjacency row per warp.
__global__ __launch_bounds__(128) void gemm1_csr_kernel(
        const float* __restrict__ X, const float* __restrict__ S,
        const float* __restrict__ W, const float* __restrict__ a,
        const float* __restrict__ adj) {
    __shared__ float xs[2][16][68];
    __shared__ float ws[2][16][128];
    int tid = threadIdx.x;

    if (blockIdx.x >= G1_BLOCKS) {
        // ---- CSR branch ----
        int warp = ((int)blockIdx.x - G1_BLOCKS) * 4 + (tid >> 5);
        int lane = tid & 31;
        const float4* arow = (const float4*)(adj + (size_t)warp * Nn);
        unsigned lmask = (1u << lane) - 1;
        int base = 0;
        for (int c0 = 0; c0 < Nn; c0 += 128) {
            float4 v = arow[(c0 >> 2) + lane];
            bool b0 = v.x > 0.f, b1 = v.y > 0.f, b2 = v.z > 0.f, b3 = v.w > 0.f;
            int col = c0 + lane * 4;
            unsigned m0 = __ballot_sync(0xffffffffu, b0);
            unsigned m1 = __ballot_sync(0xffffffffu, b1);
            unsigned m2 = __ballot_sync(0xffffffffu, b2);
            unsigned m3 = __ballot_sync(0xffffffffu, b3);
            int p = base;
            if (b0) g_cols[warp * MAXD + p + __popc(m0 & lmask)] = col;
            p += __popc(m0);
            if (b1) g_cols[warp * MAXD + p + __popc(m1 & lmask)] = col + 1;
            p += __popc(m1);
            if (b2) g_cols[warp * MAXD + p + __popc(m2 & lmask)] = col + 2;
            p += __popc(m2);
            if (b3) g_cols[warp * MAXD + p + __popc(m3 & lmask)] = col + 3;
            p += __popc(m3);
            base = p;
        }
        if (lane == 0) g_deg[warp] = base < MAXD ? base : MAXD;
        return;
    }

    // ---- GEMM1 branch ----
    int tx = tid & 15, ty = tid >> 4;
    int row0 = blockIdx.x * 64;

    float acc[8][8];
#pragma unroll
    for (int r = 0; r < 8; r++)
#pragma unroll
        for (int c = 0; c < 8; c++) acc[r][c] = 0.f;

    {   // preload tile 0
#pragma unroll
        for (int i = 0; i < 2; i++) {
            int l = tid + i * 128;
            int r = l >> 2, kq = (l & 3) * 4;
            const float* src = (kq < 64) ? X + (size_t)(row0 + r) * 64 + kq
                                         : S + (size_t)(row0 + r) * 64 + kq - 64;
            float4 v = *(const float4*)src;
            xs[0][kq + 0][r] = v.x; xs[0][kq + 1][r] = v.y;
            xs[0][kq + 2][r] = v.z; xs[0][kq + 3][r] = v.w;
        }
#pragma unroll
        for (int i = 0; i < 4; i++) {
            int l = tid + i * 128;
            int k = l >> 5, c = (l & 31) * 4;
            *(float4*)&ws[0][k][c] = *(const float4*)&W[(size_t)k * 128 + c];
        }
    }
    __syncthreads();

    for (int t = 0; t < 8; t++) {
        int buf = t & 1;
        float4 px[2], pw[4];
        if (t < 7) {
            int kt = (t + 1) * 16;
#pragma unroll
            for (int i = 0; i < 2; i++) {
                int l = tid + i * 128;
                int r = l >> 2, kq = (l & 3) * 4;
                int gk = kt + kq;
                const float* src = (gk < 64) ? X + (size_t)(row0 + r) * 64 + gk
                                             : S + (size_t)(row0 + r) * 64 + gk - 64;
                px[i] = *(const float4*)src;
            }
#pragma unroll
            for (int i = 0; i < 4; i++) {
                int l = tid + i * 128;
                int k = l >> 5, c = (l & 31) * 4;
                pw[i] = *(const float4*)&W[(size_t)(kt + k) * 128 + c];
            }
        }
#pragma unroll
        for (int k = 0; k < 16; k++) {
            float av[8], bv[8];
            *(float4*)&av[0] = *(const float4*)&xs[buf][k][ty * 8];
            *(float4*)&av[4] = *(const float4*)&xs[buf][k][ty * 8 + 4];
            *(float4*)&bv[0] = *(const float4*)&ws[buf][k][tx * 8];
            *(float4*)&bv[4] = *(const float4*)&ws[buf][k][tx * 8 + 4];
#pragma unroll
            for (int r = 0; r < 8; r++)
#pragma unroll
                for (int c = 0; c < 8; c++) acc[r][c] += av[r] * bv[c];
        }
        if (t < 7) {
            int nb = buf ^ 1;
#pragma unroll
            for (int i = 0; i < 2; i++) {
                int l = tid + i * 128;
                int r = l >> 2, kq = (l & 3) * 4;
                xs[nb][kq + 0][r] = px[i].x; xs[nb][kq + 1][r] = px[i].y;
                xs[nb][kq + 2][r] = px[i].z; xs[nb][kq + 3][r] = px[i].w;
            }
#pragma unroll
            for (int i = 0; i < 4; i++) {
                int l = tid + i * 128;
                int k = l >> 5, c = (l & 31) * 4;
                *(float4*)&ws[nb][k][c] = pw[i];
            }
            __syncthreads();
        }
    }
    float asrc[8], adst[8];
#pragma unroll
    for (int c = 0; c < 8; c++) {
        asrc[c] = __ldg(a + tx * 8 + c);
        adst[c] = __ldg(a + 128 + tx * 8 + c);
    }
#pragma unroll
    for (int r = 0; r < 8; r++) {
        int row = row0 + ty * 8 + r;
        float4 v0 = make_float4(acc[r][0], acc[r][1], acc[r][2], acc[r][3]);
        float4 v1 = make_float4(acc[r][4], acc[r][5], acc[r][6], acc[r][7]);
        *(float4*)&g_h1[(size_t)row * 128 + tx * 8]     = v0;
        *(float4*)&g_h1[(size_t)row * 128 + tx * 8 + 4] = v1;
        float ps = 0.f, pd = 0.f;
#pragma unroll
        for (int c = 0; c < 8; c++) { ps += acc[r][c] * asrc[c]; pd += acc[r][c] * adst[c]; }
#pragma unroll
        for (int o = 8; o; o >>= 1) {
            ps += __shfl_xor_sync(0xffffffffu, ps, o);
            pd += __shfl_xor_sync(0xffffffffu, pd, o);
        }
        if (tx == 0) { g_s1s[row] = ps; g_s1d[row] = pd; }
    }
}

// ---------------- GEMM2: h2 = [X|r*state] @ W2 (+ fused scores) ------------
// BM=64, BN=64, BK=16, 128 threads, 8x4/thread, grid=256. W2 smem-resident.
__global__ __launch_bounds__(128) void gemm2_kernel(
        const float* __restrict__ X,
        const float* __restrict__ W, const float* __restrict__ a) {
    __shared__ float xs[2][16][68];
    __shared__ float ws[128][64];
    const float* S = (const float*)g_rs;
    int tid = threadIdx.x;
    int tx = tid & 15, ty = tid >> 4;
    int row0 = blockIdx.x * 64;

    float acc[8][4];
#pragma unroll
    for (int r = 0; r < 8; r++)
#pragma unroll
        for (int c = 0; c < 4; c++) acc[r][c] = 0.f;

#pragma unroll
    for (int i = 0; i < 16; i++) {
        int l = tid + i * 128;
        int k = l >> 4, c = (l & 15) * 4;
        *(float4*)&ws[k][c] = *(const float4*)&W[(size_t)k * 64 + c];
    }
    {
#pragma unroll
        for (int i = 0; i < 2; i++) {
            int l = tid + i * 128;
            int r = l >> 2, kq = (l & 3) * 4;
            const float* src = (kq < 64) ? X + (size_t)(row0 + r) * 64 + kq
                                         : S + (size_t)(row0 + r) * 64 + kq - 64;
            float4 v = *(const float4*)src;
            xs[0][kq + 0][r] = v.x; xs[0][kq + 1][r] = v.y;
            xs[0][kq + 2][r] = v.z; xs[0][kq + 3][r] = v.w;
        }
    }
    __syncthreads();

    for (int t = 0; t < 8; t++) {
        int buf = t & 1;
        float4 px[2];
        if (t < 7) {
            int kt = (t + 1) * 16;
#pragma unroll
            for (int i = 0; i < 2; i++) {
                int l = tid + i * 128;
                int r = l >> 2, kq = (l & 3) * 4;
                int gk = kt + kq;
                const float* src = (gk < 64) ? X + (size_t)(row0 + r) * 64 + gk
                                             : S + (size_t)(row0 + r) * 64 + gk - 64;
                px[i] = *(const float4*)src;
            }
        }
        int kb = t * 16;
#pragma unroll
        for (int k = 0; k < 16; k++) {
            float av[8], bv[4];
            *(float4*)&av[0] = *(const float4*)&xs[buf][k][ty * 8];
            *(float4*)&av[4] = *(const float4*)&xs[buf][k][ty * 8 + 4];
            *(float4*)&bv[0] = *(const float4*)&ws[kb + k][tx * 4];
#pragma unroll
            for (int r = 0; r < 8; r++)
#pragma unroll
                for (int c = 0; c < 4; c++) acc[r][c] += av[r] * bv[c];
        }
        if (t < 7) {
            int nb = buf ^ 1;
#pragma unroll
            for (int i = 0; i < 2; i++) {
                int l = tid + i * 128;
                int r = l >> 2, kq = (l & 3) * 4;
                xs[nb][kq + 0][r] = px[i].x; xs[nb][kq + 1][r] = px[i].y;
                xs[nb][kq + 2][r] = px[i].z; xs[nb][kq + 3][r] = px[i].w;
            }
            __syncthreads();
        }
    }
    float asrc[4], adst[4];
#pragma unroll
    for (int c = 0; c < 4; c++) {
        asrc[c] = __ldg(a + tx * 4 + c);
        adst[c] = __ldg(a + 64 + tx * 4 + c);
    }
#pragma unroll
    for (int r = 0; r < 8; r++) {
        int row = row0 + ty * 8 + r;
        float4 v0 = make_float4(acc[r][0], acc[r][1], acc[r][2], acc[r][3]);
        *(float4*)&g_h2[(size_t)row * 64 + tx * 4] = v0;
        float ps = 0.f, pd = 0.f;
#pragma unroll
        for (int c = 0; c < 4; c++) { ps += acc[r][c] * asrc[c]; pd += acc[r][c] * adst[c]; }
#pragma unroll
        for (int o = 8; o; o >>= 1) {
            ps += __shfl_xor_sync(0xffffffffu, ps, o);
            pd += __shfl_xor_sync(0xffffffffu, pd, o);
        }
        if (tx == 0) { g_s2s[row] = ps; g_s2d[row] = pd; }
    }
}

// ---------------- layer-1 aggregation: unnormalized-weight gather ----------
__global__ __launch_bounds__(256) void agg1_kernel(const float* __restrict__ state) {
    __shared__ float wsh[8][MAXD];
    int warp = threadIdx.x >> 5;
    int lane = threadIdx.x & 31;
    int gw = blockIdx.x * 8 + warp;
    int b = gw >> 10, i = gw & (Nn - 1);
    int bN = b * Nn;
    int d = g_deg[i];
    const int* cl = g_cols + i * MAXD;
    float si = g_s1s[gw];
    float* w = wsh[warp];

    float m = -1e30f;
    for (int t = lane; t < d; t += 32) {
        float e = lrelu(si + __ldg(&g_s1d[bN + cl[t]]));
        w[t] = e;
        m = fmaxf(m, e);
    }
#pragma unroll
    for (int o = 16; o; o >>= 1) m = fmaxf(m, __shfl_xor_sync(0xffffffffu, m, o));
    __syncwarp();
    float Z = 0.f;
    for (int t = lane; t < d; t += 32) { float p = __expf(w[t] - m); w[t] = p; Z += p; }
#pragma unroll
    for (int o = 16; o; o >>= 1) Z += __shfl_xor_sync(0xffffffffu, Z, o);
    float invZ = 1.f / Z;
    __syncwarp();

    const float4* H = (const float4*)g_h1;
    float4 acc = make_float4(0.f, 0.f, 0.f, 0.f);
    int t = 0;
    for (; t + 4 <= d; t += 4) {
        int j0 = cl[t], j1 = cl[t+1], j2 = cl[t+2], j3 = cl[t+3];
        float w0 = w[t], w1 = w[t+1], w2 = w[t+2], w3 = w[t+3];
        float4 h0 = H[(bN + j0) * 32 + lane];
        float4 h1 = H[(bN + j1) * 32 + lane];
        float4 h2 = H[(bN + j2) * 32 + lane];
        float4 h3 = H[(bN + j3) * 32 + lane];
        acc.x += w0*h0.x + w1*h1.x + w2*h2.x + w3*h3.x;
        acc.y += w0*h0.y + w1*h1.y + w2*h2.y + w3*h3.y;
        acc.z += w0*h0.z + w1*h1.z + w2*h2.z + w3*h3.z;
        acc.w += w0*h0.w + w1*h1.w + w2*h2.w + w3*h3.w;
    }
    for (; t < d; t++) {
        float wt = w[t];
        float4 hv = H[(bN + cl[t]) * 32 + lane];
        acc.x += wt*hv.x; acc.y += wt*hv.y; acc.z += wt*hv.z; acc.w += wt*hv.w;
    }
    acc.x *= invZ; acc.y *= invZ; acc.z *= invZ; acc.w *= invZ;
    float4 g;
    g.x = 1.f / (1.f + __expf(-acc.x));
    g.y = 1.f / (1.f + __expf(-acc.y));
    g.z = 1.f / (1.f + __expf(-acc.z));
    g.w = 1.f / (1.f + __expf(-acc.w));
    if (lane < 16) {   // features [0,64): r -> store r*state
        float4 st = ((const float4*)(state + (size_t)gw * 64))[lane];
        float4 o;
        o.x = g.x*st.x; o.y = g.y*st.y; o.z = g.z*st.z; o.w = g.w*st.w;
        ((float4*)(g_rs + (size_t)gw * 64))[lane] = o;
    } else {           // features [64,128): z
        ((float4*)(g_z + (size_t)gw * 64))[lane - 16] = g;
    }
}

// ---------------- layer-2 aggregation + GRU blend: 2 batches per warp ------
// Warp handles node i for batches (2q, 2q+1). Half-warp = 16 lanes x float4 =
// one full 64-float h2 row. One LDG.128 serves both batches' gathers.
#define WPAD 272
__global__ __launch_bounds__(256) void agg2_kernel(const float* __restrict__ state,
                                                   float* __restrict__ out) {
    __shared__ float wsh[8][2][WPAD];
    int warp = threadIdx.x >> 5;
    int lane = threadIdx.x & 31;
    int half = lane >> 4;              // 0: batch 2q, 1: batch 2q+1
    int l16  = lane & 15;
    int p = blockIdx.x * 8 + warp;     // pair index in [0, 8192)
    int i = p & (Nn - 1);
    int b = ((p >> 10) << 1) + half;   // batch for this half
    int bN = b * Nn;
    int row = bN + i;
    int d = g_deg[i];
    const int* cl = g_cols + i * MAXD;
    float si = g_s2s[row];
    float* w = wsh[warp][half];

    // pass 1: scores (each half its own batch; cl[t] broadcasts across halves)
    float m = -1e30f;
    for (int t = l16; t < d; t += 16) {
        float e = lrelu(si + __ldg(&g_s2d[bN + cl[t]]));
        w[t] = e;
        m = fmaxf(m, e);
    }
#pragma unroll
    for (int o = 8; o; o >>= 1) m = fmaxf(m, __shfl_xor_sync(0xffffffffu, m, o));
    __syncwarp();
    float Z = 0.f;
    for (int t = l16; t < d; t += 16) { float pe = __expf(w[t] - m); w[t] = pe; Z += pe; }
#pragma unroll
    for (int o = 8; o; o >>= 1) Z += __shfl_xor_sync(0xffffffffu, Z, o);
    float invZ = 1.f / Z;
    __syncwarp();

    // gather: one float4 per lane; halves read their own weights (bank-disjoint)
    const float4* H = (const float4*)g_h2;   // row stride 16 float4
    int basev = bN * 16 + l16;
    float4 acc = make_float4(0.f, 0.f, 0.f, 0.f);
    int t = 0;
    for (; t + 4 <= d; t += 4) {
        int j0 = cl[t], j1 = cl[t+1], j2 = cl[t+2], j3 = cl[t+3];
        float w0 = w[t], w1 = w[t+1], w2 = w[t+2], w3 = w[t+3];
        float4 h0 = H[basev + j0 * 16];
        float4 h1 = H[basev + j1 * 16];
        float4 h2 = H[basev + j2 * 16];
        float4 h3 = H[basev + j3 * 16];
        acc.x += w0*h0.x + w1*h1.x + w2*h2.x + w3*h3.x;
        acc.y += w0*h0.y + w1*h1.y + w2*h2.y + w3*h3.y;
        acc.z += w0*h0.z + w1*h1.z + w2*h2.z + w3*h3.z;
        acc.w += w0*h0.w + w1*h1.w + w2*h2.w + w3*h3.w;
    }
    for (; t < d; t++) {
        float wt = w[t];
        float4 hv = H[basev + cl[t] * 16];
        acc.x += wt*hv.x; acc.y += wt*hv.y; acc.z += wt*hv.z; acc.w += wt*hv.w;
    }
    float hx = tanhf(acc.x * invZ), hy = tanhf(acc.y * invZ);
    float hz = tanhf(acc.z * invZ), hw = tanhf(acc.w * invZ);
    float4 zz = ((const float4*)(g_z   + (size_t)row * 64))[l16];
    float4 st = ((const float4*)(state + (size_t)row * 64))[l16];
    float4 o;
    o.x = zz.x * st.x + (1.f - zz.x) * hx;
    o.y = zz.y * st.y + (1.f - zz.y) * hy;
    o.z = zz.z * st.z + (1.f - zz.z) * hz;
    o.w = zz.w * st.w + (1.f - zz.w) * hw;
    ((float4*)(out + (size_t)row * 64))[l16] = o;
}

// ---------------- launch ---------------------------------------------------
extern "C" void kernel_launch(void* const* d_in, const int* in_sizes, int n_in,
                              void* d_out, int out_size) {
    const float* X     = (const float*)d_in[0];
    const float* state = (const float*)d_in[1];
    const float* adj   = (const float*)d_in[2];
    const float* W1    = (const float*)d_in[3];
    const float* a1    = (const float*)d_in[4];
    const float* W2    = (const float*)d_in[5];
    const float* a2    = (const float*)d_in[6];
    float* out = (float*)d_out;

    gemm1_csr_kernel<<<G1_BLOCKS + CSR_BLOCKS, 128>>>(X, state, W1, a1, adj);
    agg1_kernel<<<ROWS / 8, 256>>>(state);
    gemm2_kernel<<<ROWS / 64, 128>>>(X, W2, a2);
    agg2_kernel<<<ROWS / 16, 256>>>(state, out);
}

// round 11
// speedup vs baseline: 1.1529x; 1.1529x over previous
#include <cuda_runtime.h>
#include <math.h>

#define Bb    16
#define Nn    1024
#define Uu    64
#define MAXD  256
#define ALPHAF 0.2f
#define ROWS  (Bb*Nn)
#define G1_BLOCKS (ROWS / 64)      /* 256 gemm1 blocks */
#define CSR_BLOCKS (Nn / 4)        /* 256 csr blocks, 4 warps each */

// ---------------- scratch (device globals; no allocation allowed) ----------
__device__ float g_h1[ROWS * 128];   // layer-1 features  (8 MB)
__device__ float g_h2[ROWS * 64];    // layer-2 features  (4 MB)
__device__ float g_rs[ROWS * 64];    // r * state         (4 MB)
__device__ float g_z [ROWS * 64];    // z gate            (4 MB)
__device__ float g_s1s[ROWS], g_s1d[ROWS];
__device__ float g_s2s[ROWS], g_s2d[ROWS];
__device__ int   g_cols[Nn * MAXD];
__device__ int   g_deg [Nn];

__device__ __forceinline__ float lrelu(float x) { return x > 0.f ? x : ALPHAF * x; }

// ---------------- fused GEMM1 + CSR build ----------------------------------
// blocks [0,256): h1 = [X|state] @ W1 + fused scores (8x8/thread, dbl-buffered)
// blocks [256,512): CSR build, 4 warps/block, one adjacency row per warp.
__global__ __launch_bounds__(128) void gemm1_csr_kernel(
        const float* __restrict__ X, const float* __restrict__ S,
        const float* __restrict__ W, const float* __restrict__ a,
        const float* __restrict__ adj) {
    __shared__ float xs[2][16][68];
    __shared__ float ws[2][16][128];
    int tid = threadIdx.x;

    if (blockIdx.x >= G1_BLOCKS) {
        // ---- CSR branch ----
        int warp = ((int)blockIdx.x - G1_BLOCKS) * 4 + (tid >> 5);
        int lane = tid & 31;
        const float4* arow = (const float4*)(adj + (size_t)warp * Nn);
        unsigned lmask = (1u << lane) - 1;
        int base = 0;
        for (int c0 = 0; c0 < Nn; c0 += 128) {
            float4 v = arow[(c0 >> 2) + lane];
            bool b0 = v.x > 0.f, b1 = v.y > 0.f, b2 = v.z > 0.f, b3 = v.w > 0.f;
            int col = c0 + lane * 4;
            unsigned m0 = __ballot_sync(0xffffffffu, b0);
            unsigned m1 = __ballot_sync(0xffffffffu, b1);
            unsigned m2 = __ballot_sync(0xffffffffu, b2);
            unsigned m3 = __ballot_sync(0xffffffffu, b3);
            int p = base;
            if (b0) g_cols[warp * MAXD + p + __popc(m0 & lmask)] = col;
            p += __popc(m0);
            if (b1) g_cols[warp * MAXD + p + __popc(m1 & lmask)] = col + 1;
            p += __popc(m1);
            if (b2) g_cols[warp * MAXD + p + __popc(m2 & lmask)] = col + 2;
            p += __popc(m2);
            if (b3) g_cols[warp * MAXD + p + __popc(m3 & lmask)] = col + 3;
            p += __popc(m3);
            base = p;
        }
        if (lane == 0) g_deg[warp] = base < MAXD ? base : MAXD;
        return;
    }

    // ---- GEMM1 branch ----
    int tx = tid & 15, ty = tid >> 4;
    int row0 = blockIdx.x * 64;

    float acc[8][8];
#pragma unroll
    for (int r = 0; r < 8; r++)
#pragma unroll
        for (int c = 0; c < 8; c++) acc[r][c] = 0.f;

    {   // preload tile 0
#pragma unroll
        for (int i = 0; i < 2; i++) {
            int l = tid + i * 128;
            int r = l >> 2, kq = (l & 3) * 4;
            const float* src = (kq < 64) ? X + (size_t)(row0 + r) * 64 + kq
                                         : S + (size_t)(row0 + r) * 64 + kq - 64;
            float4 v = *(const float4*)src;
            xs[0][kq + 0][r] = v.x; xs[0][kq + 1][r] = v.y;
            xs[0][kq + 2][r] = v.z; xs[0][kq + 3][r] = v.w;
        }
#pragma unroll
        for (int i = 0; i < 4; i++) {
            int l = tid + i * 128;
            int k = l >> 5, c = (l & 31) * 4;
            *(float4*)&ws[0][k][c] = *(const float4*)&W[(size_t)k * 128 + c];
        }
    }
    __syncthreads();

    for (int t = 0; t < 8; t++) {
        int buf = t & 1;
        float4 px[2], pw[4];
        if (t < 7) {
            int kt = (t + 1) * 16;
#pragma unroll
            for (int i = 0; i < 2; i++) {
                int l = tid + i * 128;
                int r = l >> 2, kq = (l & 3) * 4;
                int gk = kt + kq;
                const float* src = (gk < 64) ? X + (size_t)(row0 + r) * 64 + gk
                                             : S + (size_t)(row0 + r) * 64 + gk - 64;
                px[i] = *(const float4*)src;
            }
#pragma unroll
            for (int i = 0; i < 4; i++) {
                int l = tid + i * 128;
                int k = l >> 5, c = (l & 31) * 4;
                pw[i] = *(const float4*)&W[(size_t)(kt + k) * 128 + c];
            }
        }
#pragma unroll
        for (int k = 0; k < 16; k++) {
            float av[8], bv[8];
            *(float4*)&av[0] = *(const float4*)&xs[buf][k][ty * 8];
            *(float4*)&av[4] = *(const float4*)&xs[buf][k][ty * 8 + 4];
            *(float4*)&bv[0] = *(const float4*)&ws[buf][k][tx * 8];
            *(float4*)&bv[4] = *(const float4*)&ws[buf][k][tx * 8 + 4];
#pragma unroll
            for (int r = 0; r < 8; r++)
#pragma unroll
                for (int c = 0; c < 8; c++) acc[r][c] += av[r] * bv[c];
        }
        if (t < 7) {
            int nb = buf ^ 1;
#pragma unroll
            for (int i = 0; i < 2; i++) {
                int l = tid + i * 128;
                int r = l >> 2, kq = (l & 3) * 4;
                xs[nb][kq + 0][r] = px[i].x; xs[nb][kq + 1][r] = px[i].y;
                xs[nb][kq + 2][r] = px[i].z; xs[nb][kq + 3][r] = px[i].w;
            }
#pragma unroll
            for (int i = 0; i < 4; i++) {
                int l = tid + i * 128;
                int k = l >> 5, c = (l & 31) * 4;
                *(float4*)&ws[nb][k][c] = pw[i];
            }
            __syncthreads();
        }
    }
    float asrc[8], adst[8];
#pragma unroll
    for (int c = 0; c < 8; c++) {
        asrc[c] = __ldg(a + tx * 8 + c);
        adst[c] = __ldg(a + 128 + tx * 8 + c);
    }
#pragma unroll
    for (int r = 0; r < 8; r++) {
        int row = row0 + ty * 8 + r;
        float4 v0 = make_float4(acc[r][0], acc[r][1], acc[r][2], acc[r][3]);
        float4 v1 = make_float4(acc[r][4], acc[r][5], acc[r][6], acc[r][7]);
        *(float4*)&g_h1[(size_t)row * 128 + tx * 8]     = v0;
        *(float4*)&g_h1[(size_t)row * 128 + tx * 8 + 4] = v1;
        float ps = 0.f, pd = 0.f;
#pragma unroll
        for (int c = 0; c < 8; c++) { ps += acc[r][c] * asrc[c]; pd += acc[r][c] * adst[c]; }
#pragma unroll
        for (int o = 8; o; o >>= 1) {
            ps += __shfl_xor_sync(0xffffffffu, ps, o);
            pd += __shfl_xor_sync(0xffffffffu, pd, o);
        }
        if (tx == 0) { g_s1s[row] = ps; g_s1d[row] = pd; }
    }
}

// ---------------- GEMM2: h2 = [X|r*state] @ W2 (+ fused scores) ------------
// BM=64, BN=64, BK=16, 128 threads, 8x4/thread, grid=256. W2 smem-resident.
__global__ __launch_bounds__(128) void gemm2_kernel(
        const float* __restrict__ X,
        const float* __restrict__ W, const float* __restrict__ a) {
    __shared__ float xs[2][16][68];
    __shared__ float ws[128][64];
    const float* S = (const float*)g_rs;
    int tid = threadIdx.x;
    int tx = tid & 15, ty = tid >> 4;
    int row0 = blockIdx.x * 64;

    float acc[8][4];
#pragma unroll
    for (int r = 0; r < 8; r++)
#pragma unroll
        for (int c = 0; c < 4; c++) acc[r][c] = 0.f;

#pragma unroll
    for (int i = 0; i < 16; i++) {
        int l = tid + i * 128;
        int k = l >> 4, c = (l & 15) * 4;
        *(float4*)&ws[k][c] = *(const float4*)&W[(size_t)k * 64 + c];
    }
    {
#pragma unroll
        for (int i = 0; i < 2; i++) {
            int l = tid + i * 128;
            int r = l >> 2, kq = (l & 3) * 4;
            const float* src = (kq < 64) ? X + (size_t)(row0 + r) * 64 + kq
                                         : S + (size_t)(row0 + r) * 64 + kq - 64;
            float4 v = *(const float4*)src;
            xs[0][kq + 0][r] = v.x; xs[0][kq + 1][r] = v.y;
            xs[0][kq + 2][r] = v.z; xs[0][kq + 3][r] = v.w;
        }
    }
    __syncthreads();

    for (int t = 0; t < 8; t++) {
        int buf = t & 1;
        float4 px[2];
        if (t < 7) {
            int kt = (t + 1) * 16;
#pragma unroll
            for (int i = 0; i < 2; i++) {
                int l = tid + i * 128;
                int r = l >> 2, kq = (l & 3) * 4;
                int gk = kt + kq;
                const float* src = (gk < 64) ? X + (size_t)(row0 + r) * 64 + gk
                                             : S + (size_t)(row0 + r) * 64 + gk - 64;
                px[i] = *(const float4*)src;
            }
        }
        int kb = t * 16;
#pragma unroll
        for (int k = 0; k < 16; k++) {
            float av[8], bv[4];
            *(float4*)&av[0] = *(const float4*)&xs[buf][k][ty * 8];
            *(float4*)&av[4] = *(const float4*)&xs[buf][k][ty * 8 + 4];
            *(float4*)&bv[0] = *(const float4*)&ws[kb + k][tx * 4];
#pragma unroll
            for (int r = 0; r < 8; r++)
#pragma unroll
                for (int c = 0; c < 4; c++) acc[r][c] += av[r] * bv[c];
        }
        if (t < 7) {
            int nb = buf ^ 1;
#pragma unroll
            for (int i = 0; i < 2; i++) {
                int l = tid + i * 128;
                int r = l >> 2, kq = (l & 3) * 4;
                xs[nb][kq + 0][r] = px[i].x; xs[nb][kq + 1][r] = px[i].y;
                xs[nb][kq + 2][r] = px[i].z; xs[nb][kq + 3][r] = px[i].w;
            }
            __syncthreads();
        }
    }
    float asrc[4], adst[4];
#pragma unroll
    for (int c = 0; c < 4; c++) {
        asrc[c] = __ldg(a + tx * 4 + c);
        adst[c] = __ldg(a + 64 + tx * 4 + c);
    }
#pragma unroll
    for (int r = 0; r < 8; r++) {
        int row = row0 + ty * 8 + r;
        float4 v0 = make_float4(acc[r][0], acc[r][1], acc[r][2], acc[r][3]);
        *(float4*)&g_h2[(size_t)row * 64 + tx * 4] = v0;
        float ps = 0.f, pd = 0.f;
#pragma unroll
        for (int c = 0; c < 4; c++) { ps += acc[r][c] * asrc[c]; pd += acc[r][c] * adst[c]; }
#pragma unroll
        for (int o = 8; o; o >>= 1) {
            ps += __shfl_xor_sync(0xffffffffu, ps, o);
            pd += __shfl_xor_sync(0xffffffffu, pd, o);
        }
        if (tx == 0) { g_s2s[row] = ps; g_s2d[row] = pd; }
    }
}

// ---------------- layer-1 aggregation: addr-precomputed gather -------------
__global__ __launch_bounds__(256) void agg1_kernel(const float* __restrict__ state) {
    __shared__ __align__(16) float wsh[8][MAXD];
    __shared__ __align__(16) int   ish[8][MAXD];
    int warp = threadIdx.x >> 5;
    int lane = threadIdx.x & 31;
    int gw = blockIdx.x * 8 + warp;
    int b = gw >> 10, i = gw & (Nn - 1);
    int bN = b * Nn;
    int d = g_deg[i];
    const int* cl = g_cols + i * MAXD;
    float si = g_s1s[gw];
    float* w = wsh[warp];
    int*   ix = ish[warp];

    // pass 1: scores + precomputed float4-row addresses
    float m = -1e30f;
    for (int t = lane; t < d; t += 32) {
        int j = cl[t];
        float e = lrelu(si + __ldg(&g_s1d[bN + j]));
        w[t] = e;
        ix[t] = (bN + j) * 32;
        m = fmaxf(m, e);
    }
#pragma unroll
    for (int o = 16; o; o >>= 1) m = fmaxf(m, __shfl_xor_sync(0xffffffffu, m, o));
    __syncwarp();
    float Z = 0.f;
    for (int t = lane; t < d; t += 32) { float p = __expf(w[t] - m); w[t] = p; Z += p; }
#pragma unroll
    for (int o = 16; o; o >>= 1) Z += __shfl_xor_sync(0xffffffffu, Z, o);
    float invZ = 1.f / Z;
    __syncwarp();

    const float4* H = (const float4*)g_h1;
    float4 acc = make_float4(0.f, 0.f, 0.f, 0.f);
    int t = 0;
    for (; t + 4 <= d; t += 4) {
        float4 wv = *(const float4*)&w[t];
        int4   iv = *(const int4*)&ix[t];
        float4 h0 = H[iv.x + lane];
        float4 h1 = H[iv.y + lane];
        float4 h2 = H[iv.z + lane];
        float4 h3 = H[iv.w + lane];
        acc.x += wv.x*h0.x + wv.y*h1.x + wv.z*h2.x + wv.w*h3.x;
        acc.y += wv.x*h0.y + wv.y*h1.y + wv.z*h2.y + wv.w*h3.y;
        acc.z += wv.x*h0.z + wv.y*h1.z + wv.z*h2.z + wv.w*h3.z;
        acc.w += wv.x*h0.w + wv.y*h1.w + wv.z*h2.w + wv.w*h3.w;
    }
    for (; t < d; t++) {
        float wt = w[t];
        float4 hv = H[ix[t] + lane];
        acc.x += wt*hv.x; acc.y += wt*hv.y; acc.z += wt*hv.z; acc.w += wt*hv.w;
    }
    acc.x *= invZ; acc.y *= invZ; acc.z *= invZ; acc.w *= invZ;
    float4 g;
    g.x = 1.f / (1.f + __expf(-acc.x));
    g.y = 1.f / (1.f + __expf(-acc.y));
    g.z = 1.f / (1.f + __expf(-acc.z));
    g.w = 1.f / (1.f + __expf(-acc.w));
    if (lane < 16) {   // features [0,64): r -> store r*state
        float4 st = ((const float4*)(state + (size_t)gw * 64))[lane];
        float4 o;
        o.x = g.x*st.x; o.y = g.y*st.y; o.z = g.z*st.z; o.w = g.w*st.w;
        ((float4*)(g_rs + (size_t)gw * 64))[lane] = o;
    } else {           // features [64,128): z
        ((float4*)(g_z + (size_t)gw * 64))[lane - 16] = g;
    }
}

// ---------------- layer-2 aggregation + GRU blend --------------------------
// One row per warp (max MLP across 16384 warps), addr-precomputed gather.
__global__ __launch_bounds__(256) void agg2_kernel(const float* __restrict__ state,
                                                   float* __restrict__ out) {
    __shared__ __align__(16) float wsh[8][MAXD];
    __shared__ __align__(16) int   ish[8][MAXD];
    int warp = threadIdx.x >> 5;
    int lane = threadIdx.x & 31;
    int gw = blockIdx.x * 8 + warp;
    int b = gw >> 10, i = gw & (Nn - 1);
    int bN = b * Nn;
    int d = g_deg[i];
    const int* cl = g_cols + i * MAXD;
    float si = g_s2s[gw];
    float* w = wsh[warp];
    int*   ix = ish[warp];

    float m = -1e30f;
    for (int t = lane; t < d; t += 32) {
        int j = cl[t];
        float e = lrelu(si + __ldg(&g_s2d[bN + j]));
        w[t] = e;
        ix[t] = (bN + j) * 32;          // float2-row units
        m = fmaxf(m, e);
    }
#pragma unroll
    for (int o = 16; o; o >>= 1) m = fmaxf(m, __shfl_xor_sync(0xffffffffu, m, o));
    __syncwarp();
    float Z = 0.f;
    for (int t = lane; t < d; t += 32) { float p = __expf(w[t] - m); w[t] = p; Z += p; }
#pragma unroll
    for (int o = 16; o; o >>= 1) Z += __shfl_xor_sync(0xffffffffu, Z, o);
    float invZ = 1.f / Z;
    __syncwarp();

    const float2* H = (const float2*)g_h2;
    float2 acc = make_float2(0.f, 0.f);
    int t = 0;
    for (; t + 4 <= d; t += 4) {
        float4 wv = *(const float4*)&w[t];
        int4   iv = *(const int4*)&ix[t];
        float2 h0 = H[iv.x + lane];
        float2 h1 = H[iv.y + lane];
        float2 h2 = H[iv.z + lane];
        float2 h3 = H[iv.w + lane];
        acc.x += wv.x*h0.x + wv.y*h1.x + wv.z*h2.x + wv.w*h3.x;
        acc.y += wv.x*h0.y + wv.y*h1.y + wv.z*h2.y + wv.w*h3.y;
    }
    for (; t < d; t++) {
        float wt = w[t];
        float2 hv = H[ix[t] + lane];
        acc.x += wt*hv.x; acc.y += wt*hv.y;
    }
    float tx = tanhf(acc.x * invZ), ty = tanhf(acc.y * invZ);
    float2 zz = ((const float2*)(g_z   + (size_t)gw * 64))[lane];
    float2 st = ((const float2*)(state + (size_t)gw * 64))[lane];
    float2 o;
    o.x = zz.x * st.x + (1.f - zz.x) * tx;
    o.y = zz.y * st.y + (1.f - zz.y) * ty;
    ((float2*)(out + (size_t)gw * 64))[lane] = o;
}

// ---------------- launch ---------------------------------------------------
extern "C" void kernel_launch(void* const* d_in, const int* in_sizes, int n_in,
                              void* d_out, int out_size) {
    const float* X     = (const float*)d_in[0];
    const float* state = (const float*)d_in[1];
    const float* adj   = (const float*)d_in[2];
    const float* W1    = (const float*)d_in[3];
    const float* a1    = (const float*)d_in[4];
    const float* W2    = (const float*)d_in[5];
    const float* a2    = (const float*)d_in[6];
    float* out = (float*)d_out;

    gemm1_csr_kernel<<<G1_BLOCKS + CSR_BLOCKS, 128>>>(X, state, W1, a1, adj);
    agg1_kernel<<<ROWS / 8, 256>>>(state);
    gemm2_kernel<<<ROWS / 64, 128>>>(X, W2, a2);
    agg2_kernel<<<ROWS / 8, 256>>>(state, out);
}